// round 12
// baseline (speedup 1.0000x reference)
#include <cuda_runtime.h>
#include <math.h>

#define NN 4
#define CC 64
#define HH 256
#define WW 256
#define OC 18          // G*K*K
#define HW (HH*WW)
#define EPSF 1e-5f

// Scratch (device globals; zero-initialized at load, kept zero by k_stats).
__device__ float g_sigma[(size_t)NN * OC * HW];   // ~18.9 MB
__device__ float g_sum[OC], g_sumsq[OC], g_mean[OC], g_rstd[OC];

// Pre-split packed weights: pair rows over padded K = 8 kb * 80 (tap 0..9, 8 ch,
// channel-innermost: k = kb*80 + tap*8 + c). uint2 = {hi bf16x2, lo bf16x2}.
__device__ uint2 g_Bp[320 * 24];

// jnp.pad mode='reflect' (mirror, edge not repeated)
__device__ __forceinline__ int refl(int i, int n) {
    return i < 0 ? -i : (i >= n ? 2 * n - 2 - i : i);
}

// split two floats into packed bf16 pairs: hi = truncate-to-bf16 (exact sub),
// lo = RN(residual). Pair low half = v0.
__device__ __forceinline__ uint2 split2(float v0, float v1) {
    unsigned u0 = __float_as_uint(v0), u1 = __float_as_uint(v1);
    unsigned hi;
    asm("prmt.b32 %0, %1, %2, 0x7632;" : "=r"(hi) : "r"(u0), "r"(u1));
    float r0 = v0 - __uint_as_float(u0 & 0xFFFF0000u);
    float r1 = v1 - __uint_as_float(u1 & 0xFFFF0000u);
    unsigned lo;
    asm("cvt.rn.bf16x2.f32 %0, %1, %2;" : "=r"(lo) : "f"(r1), "f"(r0));
    return make_uint2(hi, lo);
}

#define MMA16816(d, a, b0, b1)                                                 \
    asm volatile(                                                              \
        "mma.sync.aligned.m16n8k16.row.col.f32.bf16.bf16.f32 "                 \
        "{%0,%1,%2,%3},{%4,%5,%6,%7},{%8,%9},{%0,%1,%2,%3};"                   \
        : "+f"(d[0]), "+f"(d[1]), "+f"(d[2]), "+f"(d[3])                       \
        : "r"(a[0]), "r"(a[1]), "r"(a[2]), "r"(a[3]), "r"(b0), "r"(b1))

// ---------------------------------------------------------------------------
// Weight prep (unchanged from R11).
// ---------------------------------------------------------------------------
__global__ void k_wprep(const float* __restrict__ w) {
    int idx = blockIdx.x * 256 + threadIdx.x;
    if (idx >= 320 * 24) return;
    int kp2 = idx / 24, o = idx % 24;
    int kb = kp2 / 40, p = kp2 % 40, tap = p / 4, cp = p % 4;
    float v0 = 0.f, v1 = 0.f;
    if (tap < 9 && o < OC) {
        v0 = w[((size_t)o * CC + kb * 8 + 2 * cp) * 9 + tap];
        v1 = w[((size_t)o * CC + kb * 8 + 2 * cp + 1) * 9 + tap];
    }
    g_Bp[idx] = split2(v0, v1);
}

// ---------------------------------------------------------------------------
// Conv via mma.sync bf16 3-term split (unchanged from R11, best known).
// ---------------------------------------------------------------------------
__global__ void __launch_bounds__(256, 2) k_conv(const float* __restrict__ y) {
    __shared__ uint2 ysp[6 * 132 * 4];   // 25344 B
    __shared__ uint2 bsp[40 * 24];       // 7680 B
    __shared__ float ssum[OC], ssq[OC];

    int tid = threadIdx.x;
    int warp = tid >> 5, lane = tid & 31;
    int g = lane >> 2, t = lane & 3;

    int w0 = blockIdx.x * 128;
    int h0 = blockIdx.y * 4;
    int n  = blockIdx.z;

    if (tid < OC) { ssum[tid] = 0.f; ssq[tid] = 0.f; }

    int grow[6];
#pragma unroll
    for (int r = 0; r < 6; r++) grow[r] = refl(h0 - 1 + r, HH) * WW;

    float acc[4][3][4];
#pragma unroll
    for (int a = 0; a < 4; a++)
#pragma unroll
        for (int b = 0; b < 3; b++)
#pragma unroll
            for (int d = 0; d < 4; d++) acc[a][b][d] = 0.f;

    int hh  = warp >> 1;
    int pxb = (warp & 1) * 64;

    for (int kb = 0; kb < 8; kb++) {
        __syncthreads();
        for (int i = tid; i < 960; i += 256) bsp[i] = g_Bp[kb * 960 + i];
        const float* ybase = y + ((size_t)(n * CC + kb * 8)) * HW;
        for (int i = tid; i < 3168; i += 256) {
            int cp = i & 3, q = i >> 2;
            int row = q / 132, col = q - row * 132;
            int gw = refl(w0 - 1 + col, WW);
            const float* p0 = ybase + (size_t)(2 * cp) * HW + grow[row] + gw;
            float v0 = __ldg(p0), v1 = __ldg(p0 + HW);
            ysp[i] = split2(v0, v1);
        }
        __syncthreads();

#pragma unroll
        for (int ch = 0; ch < 5; ch++) {
            const int tapA = 2 * ch;
            const int tapB = (2 * ch + 1 < 9) ? 2 * ch + 1 : 0;
            const int trA = tapA / 3, tcA = tapA % 3;
            const int trB = tapB / 3, tcB = tapB % 3;

            int aA = ((hh + trA) * 132 + pxb + g + tcA) * 4 + t;
            int aB = ((hh + trB) * 132 + pxb + g + tcB) * 4 + t;
            int bbase = (ch * 8 + t) * 24 + g;

            uint2 b0[3], b1[3];
#pragma unroll
            for (int nt = 0; nt < 3; nt++) {
                b0[nt] = bsp[bbase + nt * 8];
                b1[nt] = bsp[bbase + 96 + nt * 8];
            }

#pragma unroll
            for (int mt = 0; mt < 4; mt++) {
                int off = mt * 64;
                uint2 x0 = ysp[aA + off];
                uint2 x1 = ysp[aA + off + 32];
                uint2 x2 = ysp[aB + off];
                uint2 x3 = ysp[aB + off + 32];
                unsigned ah[4] = {x0.x, x1.x, x2.x, x3.x};
                unsigned al[4] = {x0.y, x1.y, x2.y, x3.y};
#pragma unroll
                for (int nt = 0; nt < 3; nt++) {
                    MMA16816(acc[mt][nt], ah, b0[nt].x, b1[nt].x);
                    MMA16816(acc[mt][nt], al, b0[nt].x, b1[nt].x);
                    MMA16816(acc[mt][nt], ah, b0[nt].y, b1[nt].y);
                }
            }
        }
    }

    size_t sb = (size_t)n * OC * HW;
#pragma unroll
    for (int mt = 0; mt < 4; mt++)
#pragma unroll
        for (int nt = 0; nt < 3; nt++)
#pragma unroll
            for (int dd = 0; dd < 4; dd++) {
                int o = nt * 8 + 2 * t + (dd & 1);
                if (o < OC) {
                    int p = warp * 64 + mt * 16 + g + ((dd & 2) ? 8 : 0);
                    g_sigma[sb + (size_t)o * HW +
                            (size_t)(h0 + (p >> 7)) * WW + w0 + (p & 127)] =
                        acc[mt][nt][dd];
                }
            }

#pragma unroll
    for (int nt = 0; nt < 3; nt++)
#pragma unroll
        for (int d1 = 0; d1 < 2; d1++) {
            int o = nt * 8 + 2 * t + d1;
            float s = 0.f, q = 0.f;
#pragma unroll
            for (int mt = 0; mt < 4; mt++)
#pragma unroll
                for (int d2 = 0; d2 < 2; d2++) {
                    float v = acc[mt][nt][d2 * 2 + d1];
                    s += v; q += v * v;
                }
#pragma unroll
            for (int m = 4; m <= 16; m <<= 1) {
                s += __shfl_xor_sync(0xffffffffu, s, m);
                q += __shfl_xor_sync(0xffffffffu, q, m);
            }
            if (g == 0 && o < OC) { atomicAdd(&ssum[o], s); atomicAdd(&ssq[o], q); }
        }
    __syncthreads();
    if (tid < OC) { atomicAdd(&g_sum[tid], ssum[tid]); atomicAdd(&g_sumsq[tid], ssq[tid]); }
}

// Stats + self-reset (next graph replay sees zeros again).
__global__ void k_stats() {
    int o = threadIdx.x;
    if (o < OC) {
        float cnt = (float)((size_t)NN * HW);
        float m = g_sum[o] / cnt;
        float v = g_sumsq[o] / cnt - m * m;
        g_mean[o] = m;
        g_rstd[o] = rsqrtf(v + EPSF);
        g_sum[o] = 0.f;
        g_sumsq[o] = 0.f;
    }
}

// ---------------------------------------------------------------------------
// Stage 3a: BN + softmax(18) -> vmap (the required output, AND the filter's
// weight source). Pure streaming, 4 px/thread.
// ---------------------------------------------------------------------------
__global__ void __launch_bounds__(128) k_soft(const float* __restrict__ gamma,
                                              const float* __restrict__ beta,
                                              float* __restrict__ out) {
    int tx = threadIdx.x, ty = threadIdx.y;
    int w0 = (blockIdx.x * 32 + tx) * 4;
    int h0 = blockIdx.y * 4 + ty;
    int n  = blockIdx.z;
    size_t pix = (size_t)h0 * WW + w0;

    float4 s4[OC];
    float4 mx = make_float4(-1e30f, -1e30f, -1e30f, -1e30f);
#pragma unroll
    for (int o = 0; o < OC; o++) {
        float4 x = *(const float4*)&g_sigma[((size_t)n * OC + o) * HW + pix];
        float sc = g_rstd[o] * __ldg(&gamma[o]);
        float m  = g_mean[o], b = __ldg(&beta[o]);
        x.x = (x.x - m) * sc + b; x.y = (x.y - m) * sc + b;
        x.z = (x.z - m) * sc + b; x.w = (x.w - m) * sc + b;
        s4[o] = x;
        mx.x = fmaxf(mx.x, x.x); mx.y = fmaxf(mx.y, x.y);
        mx.z = fmaxf(mx.z, x.z); mx.w = fmaxf(mx.w, x.w);
    }
    float4 sum = make_float4(0.f, 0.f, 0.f, 0.f);
#pragma unroll
    for (int o = 0; o < OC; o++) {
        s4[o].x = __expf(s4[o].x - mx.x); sum.x += s4[o].x;
        s4[o].y = __expf(s4[o].y - mx.y); sum.y += s4[o].y;
        s4[o].z = __expf(s4[o].z - mx.z); sum.z += s4[o].z;
        s4[o].w = __expf(s4[o].w - mx.w); sum.w += s4[o].w;
    }
    float4 inv = make_float4(1.f / sum.x, 1.f / sum.y, 1.f / sum.z, 1.f / sum.w);

    float* vmap = out + (size_t)NN * CC * HW;
#pragma unroll
    for (int o = 0; o < OC; o++) {
        float4 v = make_float4(s4[o].x * inv.x, s4[o].y * inv.y,
                               s4[o].z * inv.z, s4[o].w * inv.w);
        *(float4*)&vmap[((size_t)n * OC + o) * HW + pix] = v;
    }
}

// ---------------------------------------------------------------------------
// Stage 3b: adaptive 3x3 filter. One CTA = one group's 32 channels (z = n*2+g);
// softmax weights read back from vmap (L2-resident). ~64 regs -> high occ.
// ---------------------------------------------------------------------------
__global__ void __launch_bounds__(128) k_filter(const float* __restrict__ y,
                                                float* __restrict__ out) {
    int tx = threadIdx.x, ty = threadIdx.y;
    int w0 = (blockIdx.x * 32 + tx) * 4;
    int h0 = blockIdx.y * 4 + ty;
    int n  = blockIdx.z >> 1;
    int g  = blockIdx.z & 1;
    size_t pix = (size_t)h0 * WW + w0;

    const float* vmap = out + (size_t)NN * CC * HW;
    float4 s4[9];
#pragma unroll
    for (int j = 0; j < 9; j++)
        s4[j] = *(const float4*)&vmap[((size_t)n * OC + g * 9 + j) * HW + pix];

    int rh[3];
#pragma unroll
    for (int i = 0; i < 3; i++) rh[i] = refl(h0 + i - 1, HH);
    int wl = refl(w0 - 1, WW);
    int wr = refl(w0 + 4, WW);

#pragma unroll 4
    for (int cg = 0; cg < 32; cg++) {
        int c = g * 32 + cg;
        const float* yc = y + ((size_t)(n * CC + c)) * HW;
        float4 acc = make_float4(0.f, 0.f, 0.f, 0.f);
#pragma unroll
        for (int i = 0; i < 3; i++) {
            const float* row = yc + rh[i] * WW;
            float4 m = __ldg((const float4*)(row + w0));
            float v[6];
            v[0] = __ldg(&row[wl]); v[1] = m.x; v[2] = m.y;
            v[3] = m.z; v[4] = m.w; v[5] = __ldg(&row[wr]);
#pragma unroll
            for (int j = 0; j < 3; j++) {
                float4 sw = s4[i * 3 + j];
                acc.x += v[0 + j] * sw.x;
                acc.y += v[1 + j] * sw.y;
                acc.z += v[2 + j] * sw.z;
                acc.w += v[3 + j] * sw.w;
            }
        }
        *(float4*)&out[((size_t)(n * CC + c)) * HW + pix] = acc;
    }
}

extern "C" void kernel_launch(void* const* d_in, const int* in_sizes, int n_in,
                              void* d_out, int out_size) {
    const float* y     = (const float*)d_in[0];
    const float* w     = (const float*)d_in[1];
    const float* gamma = (const float*)d_in[2];
    const float* beta  = (const float*)d_in[3];
    float* out = (float*)d_out;

    k_wprep<<<30, 256>>>(w);

    dim3 cgrd(WW / 128, HH / 4, NN);    // 512 CTAs
    k_conv<<<cgrd, 256>>>(y);

    k_stats<<<1, 32>>>();

    dim3 ablk(32, 4);
    dim3 sgrd(WW / 128, HH / 4, NN);
    k_soft<<<sgrd, ablk>>>(gamma, beta, out);

    dim3 fgrd(WW / 128, HH / 4, NN * 2);   // 1024 CTAs, one group each
    k_filter<<<fgrd, ablk>>>(y, out);
}

// round 13
// speedup vs baseline: 1.0699x; 1.0699x over previous
#include <cuda_runtime.h>
#include <math.h>

#define NN 4
#define CC 64
#define HH 256
#define WW 256
#define OC 18          // G*K*K
#define HW (HH*WW)
#define EPSF 1e-5f

// Scratch (device globals; zero-initialized at load, kept zero by k_stats).
__device__ float g_sigma[(size_t)NN * OC * HW];   // ~18.9 MB
__device__ float g_sum[OC], g_sumsq[OC], g_mean[OC], g_rstd[OC];

// Pre-split packed weights. k = kb*144 + tap*16 + c (16-ch blocks, channel-
// innermost; one k16-chunk == one tap). Pair rows: kp2 = kb*72 + tap*8 + cp,
// channels (2cp, 2cp+1). uint2 = {hi bf16x2, lo bf16x2}.
__device__ uint2 g_Bp[288 * 24];

// jnp.pad mode='reflect' (mirror, edge not repeated)
__device__ __forceinline__ int refl(int i, int n) {
    return i < 0 ? -i : (i >= n ? 2 * n - 2 - i : i);
}

// split two floats into packed bf16 pairs: hi = truncate-to-bf16 (exact sub),
// lo = RN(residual). Pair low half = v0.
__device__ __forceinline__ uint2 split2(float v0, float v1) {
    unsigned u0 = __float_as_uint(v0), u1 = __float_as_uint(v1);
    unsigned hi;
    asm("prmt.b32 %0, %1, %2, 0x7632;" : "=r"(hi) : "r"(u0), "r"(u1));
    float r0 = v0 - __uint_as_float(u0 & 0xFFFF0000u);
    float r1 = v1 - __uint_as_float(u1 & 0xFFFF0000u);
    unsigned lo;
    asm("cvt.rn.bf16x2.f32 %0, %1, %2;" : "=r"(lo) : "f"(r1), "f"(r0));
    return make_uint2(hi, lo);
}

#define MMA16816(d, a, b0, b1)                                                 \
    asm volatile(                                                              \
        "mma.sync.aligned.m16n8k16.row.col.f32.bf16.bf16.f32 "                 \
        "{%0,%1,%2,%3},{%4,%5,%6,%7},{%8,%9},{%0,%1,%2,%3};"                   \
        : "+f"(d[0]), "+f"(d[1]), "+f"(d[2]), "+f"(d[3])                       \
        : "r"(a[0]), "r"(a[1]), "r"(a[2]), "r"(a[3]), "r"(b0), "r"(b1))

// ---------------------------------------------------------------------------
// Weight prep: g_Bp[kp2][o], kp2 = kb*72 + tap*8 + cp; B = w[o][kb*16+2cp(+1)][tap]
// ---------------------------------------------------------------------------
__global__ void k_wprep(const float* __restrict__ w) {
    int idx = blockIdx.x * 256 + threadIdx.x;
    if (idx >= 288 * 24) return;
    int kp2 = idx / 24, o = idx % 24;
    int kb = kp2 / 72, p = kp2 % 72, tap = p / 8, cp = p % 8;
    float v0 = 0.f, v1 = 0.f;
    if (o < OC) {
        v0 = w[((size_t)o * CC + kb * 16 + 2 * cp) * 9 + tap];
        v1 = w[((size_t)o * CC + kb * 16 + 2 * cp + 1) * 9 + tap];
    }
    g_Bp[idx] = split2(v0, v1);
}

// ---------------------------------------------------------------------------
// Conv via mma.sync bf16 3-term split. CTA = 256 thr, tile = 128w x 4h.
// ysp[(row*132+col)*8 + cp] = split pair for channels (2cp,2cp+1) of the
// current 16-ch block at staged (row,col). One k16-chunk == one tap:
// A-frag k 2tt -> pair tt, k 8+2tt -> pair tt+4 (all at the tap's (row,col)).
// 36 chunks total, no k padding. BN stats fused.
// ---------------------------------------------------------------------------
__global__ void __launch_bounds__(256, 2) k_conv(const float* __restrict__ y) {
    extern __shared__ unsigned char smem_raw[];
    uint2* ysp = (uint2*)smem_raw;          // 6*132*8 = 6336 -> 50688 B
    uint2* bsp = ysp + 6336;                // 72*24   = 1728 -> 13824 B
    float* ssum = (float*)(bsp + 1728);
    float* ssq  = ssum + OC;

    int tid = threadIdx.x;
    int warp = tid >> 5, lane = tid & 31;
    int g = lane >> 2, t = lane & 3;

    int w0 = blockIdx.x * 128;
    int h0 = blockIdx.y * 4;
    int n  = blockIdx.z;

    if (tid < OC) { ssum[tid] = 0.f; ssq[tid] = 0.f; }

    int grow[6];
#pragma unroll
    for (int r = 0; r < 6; r++) grow[r] = refl(h0 - 1 + r, HH) * WW;

    float acc[4][3][4];
#pragma unroll
    for (int a = 0; a < 4; a++)
#pragma unroll
        for (int b = 0; b < 3; b++)
#pragma unroll
            for (int d = 0; d < 4; d++) acc[a][b][d] = 0.f;

    int hh  = warp >> 1;
    int pxb = (warp & 1) * 64;

    for (int kb = 0; kb < 4; kb++) {
        __syncthreads();
        for (int i = tid; i < 1728; i += 256) bsp[i] = g_Bp[kb * 1728 + i];
        const float* ybase = y + ((size_t)(n * CC + kb * 16)) * HW;
        for (int i = tid; i < 6336; i += 256) {
            int cp = i & 7, q = i >> 3;
            int row = q / 132, col = q - row * 132;
            int gw = refl(w0 - 1 + col, WW);
            const float* p0 = ybase + (size_t)(2 * cp) * HW + grow[row] + gw;
            float v0 = __ldg(p0), v1 = __ldg(p0 + HW);
            ysp[i] = split2(v0, v1);
        }
        __syncthreads();

#pragma unroll
        for (int tp = 0; tp < 9; tp++) {
            const int tr = tp / 3, tc = tp % 3;
            int abase = ((hh + tr) * 132 + pxb + g + tc) * 8 + t;
            int bbase = (tp * 8 + t) * 24 + g;

            uint2 b0[3], b1[3];
#pragma unroll
            for (int nt = 0; nt < 3; nt++) {
                b0[nt] = bsp[bbase + nt * 8];
                b1[nt] = bsp[bbase + 96 + nt * 8];   // pair-row +4 (k+8)
            }

#pragma unroll
            for (int mt = 0; mt < 4; mt++) {
                int off = mt * 128;                   // 16 px * 8
                uint2 x0 = ysp[abase + off];          // (px g,   k 2t..)
                uint2 x1 = ysp[abase + off + 64];     // (px g+8, k 2t..)
                uint2 x2 = ysp[abase + off + 4];      // (px g,   k 8+2t..)
                uint2 x3 = ysp[abase + off + 68];     // (px g+8, k 8+2t..)
                unsigned ah[4] = {x0.x, x1.x, x2.x, x3.x};
                unsigned al[4] = {x0.y, x1.y, x2.y, x3.y};
#pragma unroll
                for (int nt = 0; nt < 3; nt++) {
                    MMA16816(acc[mt][nt], ah, b0[nt].x, b1[nt].x);  // hi*hi
                    MMA16816(acc[mt][nt], al, b0[nt].x, b1[nt].x);  // lo*hi
                    MMA16816(acc[mt][nt], ah, b0[nt].y, b1[nt].y);  // hi*lo
                }
            }
        }
    }

    size_t sb = (size_t)n * OC * HW;
#pragma unroll
    for (int mt = 0; mt < 4; mt++)
#pragma unroll
        for (int nt = 0; nt < 3; nt++)
#pragma unroll
            for (int dd = 0; dd < 4; dd++) {
                int o = nt * 8 + 2 * t + (dd & 1);
                if (o < OC) {
                    int p = warp * 64 + mt * 16 + g + ((dd & 2) ? 8 : 0);
                    g_sigma[sb + (size_t)o * HW +
                            (size_t)(h0 + (p >> 7)) * WW + w0 + (p & 127)] =
                        acc[mt][nt][dd];
                }
            }

#pragma unroll
    for (int nt = 0; nt < 3; nt++)
#pragma unroll
        for (int d1 = 0; d1 < 2; d1++) {
            int o = nt * 8 + 2 * t + d1;
            float s = 0.f, q = 0.f;
#pragma unroll
            for (int mt = 0; mt < 4; mt++)
#pragma unroll
                for (int d2 = 0; d2 < 2; d2++) {
                    float v = acc[mt][nt][d2 * 2 + d1];
                    s += v; q += v * v;
                }
#pragma unroll
            for (int m = 4; m <= 16; m <<= 1) {
                s += __shfl_xor_sync(0xffffffffu, s, m);
                q += __shfl_xor_sync(0xffffffffu, q, m);
            }
            if (g == 0 && o < OC) { atomicAdd(&ssum[o], s); atomicAdd(&ssq[o], q); }
        }
    __syncthreads();
    if (tid < OC) { atomicAdd(&g_sum[tid], ssum[tid]); atomicAdd(&g_sumsq[tid], ssq[tid]); }
}

// Stats + self-reset (next graph replay sees zeros again).
__global__ void k_stats() {
    int o = threadIdx.x;
    if (o < OC) {
        float cnt = (float)((size_t)NN * HW);
        float m = g_sum[o] / cnt;
        float v = g_sumsq[o] / cnt - m * m;
        g_mean[o] = m;
        g_rstd[o] = rsqrtf(v + EPSF);
        g_sum[o] = 0.f;
        g_sumsq[o] = 0.f;
    }
}

// ---------------------------------------------------------------------------
// Stage 3: fused BN + softmax(18) + v_map + adaptive 3x3 filter (R11 version,
// measured best at 40 us).
// ---------------------------------------------------------------------------
__global__ void __launch_bounds__(128) k_apply(const float* __restrict__ y,
                                               const float* __restrict__ gamma,
                                               const float* __restrict__ beta,
                                               float* __restrict__ out) {
    int tx = threadIdx.x, ty = threadIdx.y;
    int w0 = (blockIdx.x * 32 + tx) * 4;
    int h0 = blockIdx.y * 4 + ty;
    int n  = blockIdx.z;
    size_t pix = (size_t)h0 * WW + w0;

    float4 s4[OC];
    float4 mx = make_float4(-1e30f, -1e30f, -1e30f, -1e30f);
#pragma unroll
    for (int o = 0; o < OC; o++) {
        float4 x = *(const float4*)&g_sigma[((size_t)n * OC + o) * HW + pix];
        float sc = g_rstd[o] * __ldg(&gamma[o]);
        float m  = g_mean[o], b = __ldg(&beta[o]);
        x.x = (x.x - m) * sc + b; x.y = (x.y - m) * sc + b;
        x.z = (x.z - m) * sc + b; x.w = (x.w - m) * sc + b;
        s4[o] = x;
        mx.x = fmaxf(mx.x, x.x); mx.y = fmaxf(mx.y, x.y);
        mx.z = fmaxf(mx.z, x.z); mx.w = fmaxf(mx.w, x.w);
    }
    float4 sum = make_float4(0.f, 0.f, 0.f, 0.f);
#pragma unroll
    for (int o = 0; o < OC; o++) {
        s4[o].x = __expf(s4[o].x - mx.x); sum.x += s4[o].x;
        s4[o].y = __expf(s4[o].y - mx.y); sum.y += s4[o].y;
        s4[o].z = __expf(s4[o].z - mx.z); sum.z += s4[o].z;
        s4[o].w = __expf(s4[o].w - mx.w); sum.w += s4[o].w;
    }
    float4 inv = make_float4(1.f / sum.x, 1.f / sum.y, 1.f / sum.z, 1.f / sum.w);
#pragma unroll
    for (int o = 0; o < OC; o++) {
        s4[o].x *= inv.x; s4[o].y *= inv.y; s4[o].z *= inv.z; s4[o].w *= inv.w;
    }

    float* vmap = out + (size_t)NN * CC * HW;
#pragma unroll
    for (int o = 0; o < OC; o++)
        *(float4*)&vmap[((size_t)n * OC + o) * HW + pix] = s4[o];

    int rh[3];
#pragma unroll
    for (int i = 0; i < 3; i++) rh[i] = refl(h0 + i - 1, HH);
    int wl = refl(w0 - 1, WW);
    int wr = refl(w0 + 4, WW);

#pragma unroll
    for (int g = 0; g < 2; g++) {
#pragma unroll 2
        for (int cg = 0; cg < 32; cg++) {
            int c = g * 32 + cg;
            const float* yc = y + ((size_t)(n * CC + c)) * HW;
            float4 acc = make_float4(0.f, 0.f, 0.f, 0.f);
#pragma unroll
            for (int i = 0; i < 3; i++) {
                const float* row = yc + rh[i] * WW;
                float4 m = __ldg((const float4*)(row + w0));
                float v[6];
                v[0] = __ldg(&row[wl]); v[1] = m.x; v[2] = m.y;
                v[3] = m.z; v[4] = m.w; v[5] = __ldg(&row[wr]);
#pragma unroll
                for (int j = 0; j < 3; j++) {
                    float4 sw = s4[g * 9 + i * 3 + j];
                    acc.x += v[0 + j] * sw.x;
                    acc.y += v[1 + j] * sw.y;
                    acc.z += v[2 + j] * sw.z;
                    acc.w += v[3 + j] * sw.w;
                }
            }
            *(float4*)&out[((size_t)(n * CC + c)) * HW + pix] = acc;
        }
    }
}

extern "C" void kernel_launch(void* const* d_in, const int* in_sizes, int n_in,
                              void* d_out, int out_size) {
    const float* y     = (const float*)d_in[0];
    const float* w     = (const float*)d_in[1];
    const float* gamma = (const float*)d_in[2];
    const float* beta  = (const float*)d_in[3];
    float* out = (float*)d_out;

    k_wprep<<<27, 256>>>(w);

    const int CONV_SMEM = 6336 * 8 + 1728 * 8 + 2 * OC * 4;  // 64656 B
    static int smem_set = 0;
    if (!smem_set) {
        cudaFuncSetAttribute(k_conv, cudaFuncAttributeMaxDynamicSharedMemorySize,
                             CONV_SMEM);
        smem_set = 1;
    }
    dim3 cgrd(WW / 128, HH / 4, NN);    // 512 CTAs
    k_conv<<<cgrd, 256, CONV_SMEM>>>(y);

    k_stats<<<1, 32>>>();

    dim3 ablk(32, 4), agrd(WW / 128, HH / 4, NN);
    k_apply<<<agrd, ablk>>>(y, gamma, beta, out);
}

// round 14
// speedup vs baseline: 1.0808x; 1.0102x over previous
#include <cuda_runtime.h>
#include <math.h>

#define NN 4
#define CC 64
#define HH 256
#define WW 256
#define OC 18          // G*K*K
#define HW (HH*WW)
#define EPSF 1e-5f

// Scratch (device globals; zero-initialized at load; g_sum/g_sumsq reset by
// k_wprep each replay).
__device__ float g_sigma[(size_t)NN * OC * HW];   // ~18.9 MB
__device__ float g_sum[OC], g_sumsq[OC];

// Pre-split packed weights: pair rows over padded K = 8 kb * 80 (tap 0..9, 8 ch,
// channel-innermost: k = kb*80 + tap*8 + c). uint2 = {hi bf16x2, lo bf16x2}.
__device__ uint2 g_Bp[320 * 24];

// jnp.pad mode='reflect' (mirror, edge not repeated)
__device__ __forceinline__ int refl(int i, int n) {
    return i < 0 ? -i : (i >= n ? 2 * n - 2 - i : i);
}

// split two floats into packed bf16 pairs: hi = truncate-to-bf16 (exact sub),
// lo = RN(residual). Pair low half = v0.
__device__ __forceinline__ uint2 split2(float v0, float v1) {
    unsigned u0 = __float_as_uint(v0), u1 = __float_as_uint(v1);
    unsigned hi;
    asm("prmt.b32 %0, %1, %2, 0x7632;" : "=r"(hi) : "r"(u0), "r"(u1));
    float r0 = v0 - __uint_as_float(u0 & 0xFFFF0000u);
    float r1 = v1 - __uint_as_float(u1 & 0xFFFF0000u);
    unsigned lo;
    asm("cvt.rn.bf16x2.f32 %0, %1, %2;" : "=r"(lo) : "f"(r1), "f"(r0));
    return make_uint2(hi, lo);
}

#define MMA16816(d, a, b0, b1)                                                 \
    asm volatile(                                                              \
        "mma.sync.aligned.m16n8k16.row.col.f32.bf16.bf16.f32 "                 \
        "{%0,%1,%2,%3},{%4,%5,%6,%7},{%8,%9},{%0,%1,%2,%3};"                   \
        : "+f"(d[0]), "+f"(d[1]), "+f"(d[2]), "+f"(d[3])                       \
        : "r"(a[0]), "r"(a[1]), "r"(a[2]), "r"(a[3]), "r"(b0), "r"(b1))

// ---------------------------------------------------------------------------
// Weight prep (R11 layout) + BN accumulator reset for this replay.
// ---------------------------------------------------------------------------
__global__ void k_wprep(const float* __restrict__ w) {
    int idx = blockIdx.x * 256 + threadIdx.x;
    if (blockIdx.x == 0 && threadIdx.x < OC) {
        g_sum[threadIdx.x] = 0.f;
        g_sumsq[threadIdx.x] = 0.f;
    }
    if (idx >= 320 * 24) return;
    int kp2 = idx / 24, o = idx % 24;
    int kb = kp2 / 40, p = kp2 % 40, tap = p / 4, cp = p % 4;
    float v0 = 0.f, v1 = 0.f;
    if (tap < 9 && o < OC) {
        v0 = w[((size_t)o * CC + kb * 8 + 2 * cp) * 9 + tap];
        v1 = w[((size_t)o * CC + kb * 8 + 2 * cp + 1) * 9 + tap];
    }
    g_Bp[idx] = split2(v0, v1);
}

// ---------------------------------------------------------------------------
// Conv via mma.sync bf16 3-term split (exact R11 version, best measured).
// ---------------------------------------------------------------------------
__global__ void __launch_bounds__(256, 2) k_conv(const float* __restrict__ y) {
    __shared__ uint2 ysp[6 * 132 * 4];   // 25344 B
    __shared__ uint2 bsp[40 * 24];       // 7680 B
    __shared__ float ssum[OC], ssq[OC];

    int tid = threadIdx.x;
    int warp = tid >> 5, lane = tid & 31;
    int g = lane >> 2, t = lane & 3;

    int w0 = blockIdx.x * 128;
    int h0 = blockIdx.y * 4;
    int n  = blockIdx.z;

    if (tid < OC) { ssum[tid] = 0.f; ssq[tid] = 0.f; }

    int grow[6];
#pragma unroll
    for (int r = 0; r < 6; r++) grow[r] = refl(h0 - 1 + r, HH) * WW;

    float acc[4][3][4];
#pragma unroll
    for (int a = 0; a < 4; a++)
#pragma unroll
        for (int b = 0; b < 3; b++)
#pragma unroll
            for (int d = 0; d < 4; d++) acc[a][b][d] = 0.f;

    int hh  = warp >> 1;
    int pxb = (warp & 1) * 64;

    for (int kb = 0; kb < 8; kb++) {
        __syncthreads();
        for (int i = tid; i < 960; i += 256) bsp[i] = g_Bp[kb * 960 + i];
        const float* ybase = y + ((size_t)(n * CC + kb * 8)) * HW;
        for (int i = tid; i < 3168; i += 256) {
            int cp = i & 3, q = i >> 2;
            int row = q / 132, col = q - row * 132;
            int gw = refl(w0 - 1 + col, WW);
            const float* p0 = ybase + (size_t)(2 * cp) * HW + grow[row] + gw;
            float v0 = __ldg(p0), v1 = __ldg(p0 + HW);
            ysp[i] = split2(v0, v1);
        }
        __syncthreads();

#pragma unroll
        for (int ch = 0; ch < 5; ch++) {
            const int tapA = 2 * ch;
            const int tapB = (2 * ch + 1 < 9) ? 2 * ch + 1 : 0;
            const int trA = tapA / 3, tcA = tapA % 3;
            const int trB = tapB / 3, tcB = tapB % 3;

            int aA = ((hh + trA) * 132 + pxb + g + tcA) * 4 + t;
            int aB = ((hh + trB) * 132 + pxb + g + tcB) * 4 + t;
            int bbase = (ch * 8 + t) * 24 + g;

            uint2 b0[3], b1[3];
#pragma unroll
            for (int nt = 0; nt < 3; nt++) {
                b0[nt] = bsp[bbase + nt * 8];
                b1[nt] = bsp[bbase + 96 + nt * 8];
            }

#pragma unroll
            for (int mt = 0; mt < 4; mt++) {
                int off = mt * 64;
                uint2 x0 = ysp[aA + off];
                uint2 x1 = ysp[aA + off + 32];
                uint2 x2 = ysp[aB + off];
                uint2 x3 = ysp[aB + off + 32];
                unsigned ah[4] = {x0.x, x1.x, x2.x, x3.x};
                unsigned al[4] = {x0.y, x1.y, x2.y, x3.y};
#pragma unroll
                for (int nt = 0; nt < 3; nt++) {
                    MMA16816(acc[mt][nt], ah, b0[nt].x, b1[nt].x);
                    MMA16816(acc[mt][nt], al, b0[nt].x, b1[nt].x);
                    MMA16816(acc[mt][nt], ah, b0[nt].y, b1[nt].y);
                }
            }
        }
    }

    size_t sb = (size_t)n * OC * HW;
#pragma unroll
    for (int mt = 0; mt < 4; mt++)
#pragma unroll
        for (int nt = 0; nt < 3; nt++)
#pragma unroll
            for (int dd = 0; dd < 4; dd++) {
                int o = nt * 8 + 2 * t + (dd & 1);
                if (o < OC) {
                    int p = warp * 64 + mt * 16 + g + ((dd & 2) ? 8 : 0);
                    g_sigma[sb + (size_t)o * HW +
                            (size_t)(h0 + (p >> 7)) * WW + w0 + (p & 127)] =
                        acc[mt][nt][dd];
                }
            }

#pragma unroll
    for (int nt = 0; nt < 3; nt++)
#pragma unroll
        for (int d1 = 0; d1 < 2; d1++) {
            int o = nt * 8 + 2 * t + d1;
            float s = 0.f, q = 0.f;
#pragma unroll
            for (int mt = 0; mt < 4; mt++)
#pragma unroll
                for (int d2 = 0; d2 < 2; d2++) {
                    float v = acc[mt][nt][d2 * 2 + d1];
                    s += v; q += v * v;
                }
#pragma unroll
            for (int m = 4; m <= 16; m <<= 1) {
                s += __shfl_xor_sync(0xffffffffu, s, m);
                q += __shfl_xor_sync(0xffffffffu, q, m);
            }
            if (g == 0 && o < OC) { atomicAdd(&ssum[o], s); atomicAdd(&ssq[o], q); }
        }
    __syncthreads();
    if (tid < OC) { atomicAdd(&g_sum[tid], ssum[tid]); atomicAdd(&g_sumsq[tid], ssq[tid]); }
}

// ---------------------------------------------------------------------------
// Stage 3: BN + softmax(18) + v_map + adaptive 3x3 filter. 4 px/thread.
// Multi-pass softmax (max pass, sum pass, per-group normalize+filter pass) so
// only 9 float4 softmax values are ever live -> low regs, high occupancy.
// BN stats computed inline from g_sum/g_sumsq (k_stats launch eliminated).
// ---------------------------------------------------------------------------
__global__ void __launch_bounds__(128) k_apply(const float* __restrict__ y,
                                               const float* __restrict__ gamma,
                                               const float* __restrict__ beta,
                                               float* __restrict__ out) {
    __shared__ float smean[OC], sscale[OC], sbeta[OC];

    int tx = threadIdx.x, ty = threadIdx.y;
    int tid = ty * 32 + tx;
    if (tid < OC) {
        float cnt = (float)((size_t)NN * HW);
        float m = g_sum[tid] / cnt;
        float v = g_sumsq[tid] / cnt - m * m;
        smean[tid]  = m;
        sscale[tid] = rsqrtf(v + EPSF) * __ldg(&gamma[tid]);
        sbeta[tid]  = __ldg(&beta[tid]);
    }
    __syncthreads();

    int w0 = (blockIdx.x * 32 + tx) * 4;
    int h0 = blockIdx.y * 4 + ty;
    int n  = blockIdx.z;
    size_t pix = (size_t)h0 * WW + w0;
    const float* sig = &g_sigma[(size_t)n * OC * HW + pix];

    // pass 1: max
    float4 mx = make_float4(-1e30f, -1e30f, -1e30f, -1e30f);
#pragma unroll
    for (int o = 0; o < OC; o++) {
        float4 x = *(const float4*)&sig[(size_t)o * HW];
        float sc = sscale[o], m = smean[o], b = sbeta[o];
        mx.x = fmaxf(mx.x, (x.x - m) * sc + b);
        mx.y = fmaxf(mx.y, (x.y - m) * sc + b);
        mx.z = fmaxf(mx.z, (x.z - m) * sc + b);
        mx.w = fmaxf(mx.w, (x.w - m) * sc + b);
    }
    // pass 2: sum of exp (values discarded; reloads are L2/L1 hits)
    float4 sum = make_float4(0.f, 0.f, 0.f, 0.f);
#pragma unroll
    for (int o = 0; o < OC; o++) {
        float4 x = *(const float4*)&sig[(size_t)o * HW];
        float sc = sscale[o], m = smean[o], b = sbeta[o];
        sum.x += __expf((x.x - m) * sc + b - mx.x);
        sum.y += __expf((x.y - m) * sc + b - mx.y);
        sum.z += __expf((x.z - m) * sc + b - mx.z);
        sum.w += __expf((x.w - m) * sc + b - mx.w);
    }
    float4 inv = make_float4(1.f / sum.x, 1.f / sum.y, 1.f / sum.z, 1.f / sum.w);

    int rh[3];
#pragma unroll
    for (int i = 0; i < 3; i++) rh[i] = refl(h0 + i - 1, HH);
    int wl = refl(w0 - 1, WW);
    int wr = refl(w0 + 4, WW);

    float* vmap = out + (size_t)NN * CC * HW;

    // pass 3: per group — normalize 9 channels, write vmap, filter
#pragma unroll
    for (int g = 0; g < 2; g++) {
        float4 s4[9];
#pragma unroll
        for (int j = 0; j < 9; j++) {
            int o = g * 9 + j;
            float4 x = *(const float4*)&sig[(size_t)o * HW];
            float sc = sscale[o], m = smean[o], b = sbeta[o];
            s4[j].x = __expf((x.x - m) * sc + b - mx.x) * inv.x;
            s4[j].y = __expf((x.y - m) * sc + b - mx.y) * inv.y;
            s4[j].z = __expf((x.z - m) * sc + b - mx.z) * inv.z;
            s4[j].w = __expf((x.w - m) * sc + b - mx.w) * inv.w;
            *(float4*)&vmap[((size_t)n * OC + o) * HW + pix] = s4[j];
        }

#pragma unroll 2
        for (int cg = 0; cg < 32; cg++) {
            int c = g * 32 + cg;
            const float* yc = y + ((size_t)(n * CC + c)) * HW;
            float4 acc = make_float4(0.f, 0.f, 0.f, 0.f);
#pragma unroll
            for (int i = 0; i < 3; i++) {
                const float* row = yc + rh[i] * WW;
                float4 m = __ldg((const float4*)(row + w0));
                float v[6];
                v[0] = __ldg(&row[wl]); v[1] = m.x; v[2] = m.y;
                v[3] = m.z; v[4] = m.w; v[5] = __ldg(&row[wr]);
#pragma unroll
                for (int j = 0; j < 3; j++) {
                    float4 sw = s4[i * 3 + j];
                    acc.x += v[0 + j] * sw.x;
                    acc.y += v[1 + j] * sw.y;
                    acc.z += v[2 + j] * sw.z;
                    acc.w += v[3 + j] * sw.w;
                }
            }
            *(float4*)&out[((size_t)(n * CC + c)) * HW + pix] = acc;
        }
    }
}

extern "C" void kernel_launch(void* const* d_in, const int* in_sizes, int n_in,
                              void* d_out, int out_size) {
    const float* y     = (const float*)d_in[0];
    const float* w     = (const float*)d_in[1];
    const float* gamma = (const float*)d_in[2];
    const float* beta  = (const float*)d_in[3];
    float* out = (float*)d_out;

    k_wprep<<<30, 256>>>(w);

    dim3 cgrd(WW / 128, HH / 4, NN);    // 512 CTAs
    k_conv<<<cgrd, 256>>>(y);

    dim3 ablk(32, 4), agrd(WW / 128, HH / 4, NN);
    k_apply<<<agrd, ablk>>>(y, gamma, beta, out);
}

// round 15
// speedup vs baseline: 1.2864x; 1.1903x over previous
#include <cuda_runtime.h>
#include <cuda_fp16.h>
#include <math.h>

#define NN 4
#define CC 64
#define HH 256
#define WW 256
#define OC 18          // G*K*K
#define HW (HH*WW)
#define EPSF 1e-5f

// Scratch (device globals; zero-initialized at load; self-resetting).
__device__ float g_sigma[(size_t)NN * OC * HW];   // ~18.9 MB
__device__ float g_sum[OC], g_sumsq[OC], g_mean[OC], g_rstd[OC];
__device__ unsigned g_done;

// jnp.pad mode='reflect' (mirror, edge not repeated)
__device__ __forceinline__ int refl(int i, int n) {
    return i < 0 ? -i : (i >= n ? 2 * n - 2 - i : i);
}

// split two floats into packed f16 pairs: hi = RN(f16), lo = RN(residual).
__device__ __forceinline__ uint2 split2h(float v0, float v1) {
    __half2 h = __floats2half2_rn(v0, v1);
    float r0 = v0 - __half2float(__low2half(h));
    float r1 = v1 - __half2float(__high2half(h));
    __half2 l = __floats2half2_rn(r0, r1);
    uint2 r;
    r.x = *reinterpret_cast<unsigned*>(&h);
    r.y = *reinterpret_cast<unsigned*>(&l);
    return r;
}

#define MMAF16(d, a, b0, b1)                                                   \
    asm volatile(                                                              \
        "mma.sync.aligned.m16n8k16.row.col.f32.f16.f16.f32 "                   \
        "{%0,%1,%2,%3},{%4,%5,%6,%7},{%8,%9},{%0,%1,%2,%3};"                   \
        : "+f"(d[0]), "+f"(d[1]), "+f"(d[2]), "+f"(d[3])                       \
        : "r"(a[0]), "r"(a[1]), "r"(a[2]), "r"(a[3]), "r"(b0), "r"(b1))

// ---------------------------------------------------------------------------
// Conv via mma.sync f16, 2-term split (A hi/lo x B fp16). R11 tiling:
// CTA = 256 thr, tile 128w x 4h; k = kb*80 + tap*8 + c (tap 0..9, tap9 pad).
// Weights converted inline (no prep kernel); BN stats finalized by last CTA.
// ---------------------------------------------------------------------------
__global__ void __launch_bounds__(256, 2) k_conv(const float* __restrict__ y,
                                                 const float* __restrict__ wconv) {
    __shared__ uint2 ysp[6 * 132 * 4];       // 25344 B
    __shared__ unsigned bsp[40 * 24];        // 3840 B
    __shared__ float ssum[OC], ssq[OC];
    __shared__ unsigned slast;

    int tid = threadIdx.x;
    int warp = tid >> 5, lane = tid & 31;
    int g = lane >> 2, t = lane & 3;

    int w0 = blockIdx.x * 128;
    int h0 = blockIdx.y * 4;
    int n  = blockIdx.z;

    if (tid < OC) { ssum[tid] = 0.f; ssq[tid] = 0.f; }

    int grow[6];
#pragma unroll
    for (int r = 0; r < 6; r++) grow[r] = refl(h0 - 1 + r, HH) * WW;

    float acc[4][3][4];
#pragma unroll
    for (int a = 0; a < 4; a++)
#pragma unroll
        for (int b = 0; b < 3; b++)
#pragma unroll
            for (int d = 0; d < 4; d++) acc[a][b][d] = 0.f;

    int hh  = warp >> 1;
    int pxb = (warp & 1) * 64;

    for (int kb = 0; kb < 8; kb++) {
        __syncthreads();
        // stage B inline: bsp[kp2*24+o] = f16x2(w[o][kb*8+2cp], w[o][kb*8+2cp+1]) at tap
        for (int i = tid; i < 960; i += 256) {
            int o = i % 24, kp2 = i / 24;
            int tap = kp2 >> 2, cp = kp2 & 3;
            float v0 = 0.f, v1 = 0.f;
            if (tap < 9 && o < OC) {
                v0 = wconv[((size_t)o * CC + kb * 8 + 2 * cp) * 9 + tap];
                v1 = wconv[((size_t)o * CC + kb * 8 + 2 * cp + 1) * 9 + tap];
            }
            __half2 h = __floats2half2_rn(v0, v1);
            bsp[i] = *reinterpret_cast<unsigned*>(&h);
        }
        // stage + split y: 6 rows x 132 cols x 4 channel-pairs
        const float* ybase = y + ((size_t)(n * CC + kb * 8)) * HW;
        for (int i = tid; i < 3168; i += 256) {
            int cp = i & 3, q = i >> 2;
            int row = q / 132, col = q - row * 132;
            int gw = refl(w0 - 1 + col, WW);
            const float* p0 = ybase + (size_t)(2 * cp) * HW + grow[row] + gw;
            float v0 = __ldg(p0), v1 = __ldg(p0 + HW);
            ysp[i] = split2h(v0, v1);
        }
        __syncthreads();

#pragma unroll
        for (int ch = 0; ch < 5; ch++) {
            const int tapA = 2 * ch;
            const int tapB = (2 * ch + 1 < 9) ? 2 * ch + 1 : 0;  // ch4 pad: B=0
            const int trA = tapA / 3, tcA = tapA % 3;
            const int trB = tapB / 3, tcB = tapB % 3;

            int aA = ((hh + trA) * 132 + pxb + g + tcA) * 4 + t;
            int aB = ((hh + trB) * 132 + pxb + g + tcB) * 4 + t;
            int bbase = (ch * 8 + t) * 24 + g;

            unsigned b0[3], b1[3];
#pragma unroll
            for (int nt = 0; nt < 3; nt++) {
                b0[nt] = bsp[bbase + nt * 8];
                b1[nt] = bsp[bbase + 96 + nt * 8];   // pair-row +4 (k+8)
            }

#pragma unroll
            for (int mt = 0; mt < 4; mt++) {
                int off = mt * 64;
                uint2 x0 = ysp[aA + off];
                uint2 x1 = ysp[aA + off + 32];
                uint2 x2 = ysp[aB + off];
                uint2 x3 = ysp[aB + off + 32];
                unsigned ah[4] = {x0.x, x1.x, x2.x, x3.x};
                unsigned al[4] = {x0.y, x1.y, x2.y, x3.y};
#pragma unroll
                for (int nt = 0; nt < 3; nt++) {
                    MMAF16(acc[mt][nt], ah, b0[nt], b1[nt]);  // hi * B
                    MMAF16(acc[mt][nt], al, b0[nt], b1[nt]);  // lo * B
                }
            }
        }
    }

    size_t sb = (size_t)n * OC * HW;
#pragma unroll
    for (int mt = 0; mt < 4; mt++)
#pragma unroll
        for (int nt = 0; nt < 3; nt++)
#pragma unroll
            for (int dd = 0; dd < 4; dd++) {
                int o = nt * 8 + 2 * t + (dd & 1);
                if (o < OC) {
                    int p = warp * 64 + mt * 16 + g + ((dd & 2) ? 8 : 0);
                    g_sigma[sb + (size_t)o * HW +
                            (size_t)(h0 + (p >> 7)) * WW + w0 + (p & 127)] =
                        acc[mt][nt][dd];
                }
            }

#pragma unroll
    for (int nt = 0; nt < 3; nt++)
#pragma unroll
        for (int d1 = 0; d1 < 2; d1++) {
            int o = nt * 8 + 2 * t + d1;
            float s = 0.f, q = 0.f;
#pragma unroll
            for (int mt = 0; mt < 4; mt++)
#pragma unroll
                for (int d2 = 0; d2 < 2; d2++) {
                    float v = acc[mt][nt][d2 * 2 + d1];
                    s += v; q += v * v;
                }
#pragma unroll
            for (int m = 4; m <= 16; m <<= 1) {
                s += __shfl_xor_sync(0xffffffffu, s, m);
                q += __shfl_xor_sync(0xffffffffu, q, m);
            }
            if (g == 0 && o < OC) { atomicAdd(&ssum[o], s); atomicAdd(&ssq[o], q); }
        }
    __syncthreads();
    if (tid < OC) { atomicAdd(&g_sum[tid], ssum[tid]); atomicAdd(&g_sumsq[tid], ssq[tid]); }

    // last CTA finalizes BN stats and resets accumulators (graph-deterministic)
    __threadfence();
    if (tid == 0) {
        unsigned total = gridDim.x * gridDim.y * gridDim.z;
        slast = (atomicAdd(&g_done, 1u) == total - 1u);
    }
    __syncthreads();
    if (slast) {
        if (tid < OC) {
            float cnt = (float)((size_t)NN * HW);
            float s = atomicAdd(&g_sum[tid], 0.f);
            float q = atomicAdd(&g_sumsq[tid], 0.f);
            float m = s / cnt;
            float v = q / cnt - m * m;
            g_mean[tid] = m;
            g_rstd[tid] = rsqrtf(v + EPSF);
            atomicExch(&g_sum[tid], 0.f);
            atomicExch(&g_sumsq[tid], 0.f);
        }
        if (tid == 0) g_done = 0;
    }
}

// ---------------------------------------------------------------------------
// Stage 3: fused BN + softmax(18) + v_map + adaptive 3x3 filter (R11 version,
// measured best at 40 us).
// ---------------------------------------------------------------------------
__global__ void __launch_bounds__(128) k_apply(const float* __restrict__ y,
                                               const float* __restrict__ gamma,
                                               const float* __restrict__ beta,
                                               float* __restrict__ out) {
    int tx = threadIdx.x, ty = threadIdx.y;
    int w0 = (blockIdx.x * 32 + tx) * 4;
    int h0 = blockIdx.y * 4 + ty;
    int n  = blockIdx.z;
    size_t pix = (size_t)h0 * WW + w0;

    float4 s4[OC];
    float4 mx = make_float4(-1e30f, -1e30f, -1e30f, -1e30f);
#pragma unroll
    for (int o = 0; o < OC; o++) {
        float4 x = *(const float4*)&g_sigma[((size_t)n * OC + o) * HW + pix];
        float sc = g_rstd[o] * __ldg(&gamma[o]);
        float m  = g_mean[o], b = __ldg(&beta[o]);
        x.x = (x.x - m) * sc + b; x.y = (x.y - m) * sc + b;
        x.z = (x.z - m) * sc + b; x.w = (x.w - m) * sc + b;
        s4[o] = x;
        mx.x = fmaxf(mx.x, x.x); mx.y = fmaxf(mx.y, x.y);
        mx.z = fmaxf(mx.z, x.z); mx.w = fmaxf(mx.w, x.w);
    }
    float4 sum = make_float4(0.f, 0.f, 0.f, 0.f);
#pragma unroll
    for (int o = 0; o < OC; o++) {
        s4[o].x = __expf(s4[o].x - mx.x); sum.x += s4[o].x;
        s4[o].y = __expf(s4[o].y - mx.y); sum.y += s4[o].y;
        s4[o].z = __expf(s4[o].z - mx.z); sum.z += s4[o].z;
        s4[o].w = __expf(s4[o].w - mx.w); sum.w += s4[o].w;
    }
    float4 inv = make_float4(1.f / sum.x, 1.f / sum.y, 1.f / sum.z, 1.f / sum.w);
#pragma unroll
    for (int o = 0; o < OC; o++) {
        s4[o].x *= inv.x; s4[o].y *= inv.y; s4[o].z *= inv.z; s4[o].w *= inv.w;
    }

    float* vmap = out + (size_t)NN * CC * HW;
#pragma unroll
    for (int o = 0; o < OC; o++)
        *(float4*)&vmap[((size_t)n * OC + o) * HW + pix] = s4[o];

    int rh[3];
#pragma unroll
    for (int i = 0; i < 3; i++) rh[i] = refl(h0 + i - 1, HH);
    int wl = refl(w0 - 1, WW);
    int wr = refl(w0 + 4, WW);

#pragma unroll
    for (int g = 0; g < 2; g++) {
#pragma unroll 2
        for (int cg = 0; cg < 32; cg++) {
            int c = g * 32 + cg;
            const float* yc = y + ((size_t)(n * CC + c)) * HW;
            float4 acc = make_float4(0.f, 0.f, 0.f, 0.f);
#pragma unroll
            for (int i = 0; i < 3; i++) {
                const float* row = yc + rh[i] * WW;
                float4 m = __ldg((const float4*)(row + w0));
                float v[6];
                v[0] = __ldg(&row[wl]); v[1] = m.x; v[2] = m.y;
                v[3] = m.z; v[4] = m.w; v[5] = __ldg(&row[wr]);
#pragma unroll
                for (int j = 0; j < 3; j++) {
                    float4 sw = s4[g * 9 + i * 3 + j];
                    acc.x += v[0 + j] * sw.x;
                    acc.y += v[1 + j] * sw.y;
                    acc.z += v[2 + j] * sw.z;
                    acc.w += v[3 + j] * sw.w;
                }
            }
            *(float4*)&out[((size_t)(n * CC + c)) * HW + pix] = acc;
        }
    }
}

extern "C" void kernel_launch(void* const* d_in, const int* in_sizes, int n_in,
                              void* d_out, int out_size) {
    const float* y     = (const float*)d_in[0];
    const float* w     = (const float*)d_in[1];
    const float* gamma = (const float*)d_in[2];
    const float* beta  = (const float*)d_in[3];
    float* out = (float*)d_out;

    dim3 cgrd(WW / 128, HH / 4, NN);    // 512 CTAs
    k_conv<<<cgrd, 256>>>(y, w);

    dim3 ablk(32, 4), agrd(WW / 128, HH / 4, NN);
    k_apply<<<agrd, ablk>>>(y, gamma, beta, out);
}